// round 10
// baseline (speedup 1.0000x reference)
#include <cuda_runtime.h>
#include <cuda_fp16.h>
#include <mma.h>
#include <cstdint>

using namespace nvcuda;

// Problem constants
#define Bv 4
#define Sv 2048
#define Hv 16
#define DKv 128
#define DMv 2048
#define Mv (Bv * Sv)  // 8192

// ---------------- device scratch (static, allocation-free) ----------------
__device__ __half g_Xh [Mv * DMv];
__device__ __half g_Wqh[DMv * DMv];
__device__ __half g_Wkh[DMv * DMv];
__device__ __half g_Wvh[DMv * DMv];
__device__ __half g_Woh[DMv * DMv];
__device__ __half g_Q  [Mv * DMv];
__device__ __half g_K  [Mv * DMv];
__device__ __half g_V  [Mv * DMv];
__device__ __half g_Ch [Mv * DMv];

// ---------------- cp.async helpers ----------------
__device__ __forceinline__ void cp16(void* s, const void* g) {
    unsigned int sa = (unsigned int)__cvta_generic_to_shared(s);
    asm volatile("cp.async.cg.shared.global [%0], [%1], 16;\n" :: "r"(sa), "l"(g));
}
__device__ __forceinline__ void cp_commit() { asm volatile("cp.async.commit_group;\n"); }
template <int N>
__device__ __forceinline__ void cp_wait() { asm volatile("cp.async.wait_group %0;\n" :: "n"(N)); }

// ---------------- fp32 -> fp16 convert (vector 8) ----------------
__global__ void f2h_kernel(const float4* __restrict__ in, uint4* __restrict__ out, int n8) {
    int i = blockIdx.x * blockDim.x + threadIdx.x;
    int stride = gridDim.x * blockDim.x;
    for (; i < n8; i += stride) {
        float4 a = in[i * 2], b = in[i * 2 + 1];
        __half2 h0 = __floats2half2_rn(a.x, a.y);
        __half2 h1 = __floats2half2_rn(a.z, a.w);
        __half2 h2 = __floats2half2_rn(b.x, b.y);
        __half2 h3 = __floats2half2_rn(b.z, b.w);
        uint4 o;
        o.x = *(unsigned int*)&h0; o.y = *(unsigned int*)&h1;
        o.z = *(unsigned int*)&h2; o.w = *(unsigned int*)&h3;
        out[i] = o;
    }
}

// ---------------- GEMM: block tile 128x256, warp tile 64x64, BK=64, 3-stage ----------------
// 8 warps: wr = warp>>2 (0..1) -> 64 rows, wc = warp&3 (0..3) -> 64 cols.
// C[M,N] = A[M,K] * B[N,K]^T
#define BK 64
#define KSTR 72                       // halves: 64 + 8 pad
#define ABUF (128 * KSTR)
#define BBUF (256 * KSTR)
#define NSTG 3
#define GEMM_SMEM (NSTG * (ABUF + BBUF) * 2)  // 165888 bytes

__device__ __forceinline__ void load_tiles(
    const __half* __restrict__ A, const __half* __restrict__ B, int Kdim,
    int bm, int bn, __half* As, __half* Bs, int stg, int k0, int tid) {
    // A: 128 rows x 64 halves = 1024 uint4
#pragma unroll
    for (int t = 0; t < 4; t++) {
        int v = tid + t * 256;
        int r = v >> 3;
        int c = (v & 7) * 8;
        cp16(&As[stg * ABUF + r * KSTR + c], &A[(size_t)(bm + r) * Kdim + k0 + c]);
    }
    // B: 256 rows x 64 halves = 2048 uint4
#pragma unroll
    for (int t = 0; t < 8; t++) {
        int v = tid + t * 256;
        int r = v >> 3;
        int c = (v & 7) * 8;
        cp16(&Bs[stg * BBUF + r * KSTR + c], &B[(size_t)(bn + r) * Kdim + k0 + c]);
    }
    cp_commit();
}

__device__ __forceinline__ void gemm_mainloop(
    const __half* __restrict__ A, const __half* __restrict__ B, int Kdim,
    int bm, int bn, __half* As, __half* Bs,
    wmma::fragment<wmma::accumulator, 16, 16, 16, float> acc[4][4],
    int tid, int wr, int wc) {
    const int KT = Kdim / BK;
    load_tiles(A, B, Kdim, bm, bn, As, Bs, 0, 0, tid);
    load_tiles(A, B, Kdim, bm, bn, As, Bs, 1, BK, tid);
    int stg = 0;
    for (int kt = 0; kt < KT; ++kt) {
        cp_wait<1>();
        __syncthreads();
        const __half* Ab = &As[stg * ABUF];
        const __half* Bb = &Bs[stg * BBUF];
#pragma unroll
        for (int kk = 0; kk < BK; kk += 16) {
            wmma::fragment<wmma::matrix_b, 16, 16, 16, __half, wmma::col_major> bf[4];
#pragma unroll
            for (int j = 0; j < 4; j++)
                wmma::load_matrix_sync(bf[j], &Bb[(wc * 64 + j * 16) * KSTR + kk], KSTR);
#pragma unroll
            for (int i = 0; i < 4; i++) {
                wmma::fragment<wmma::matrix_a, 16, 16, 16, __half, wmma::row_major> af;
                wmma::load_matrix_sync(af, &Ab[(wr * 64 + i * 16) * KSTR + kk], KSTR);
#pragma unroll
                for (int j = 0; j < 4; j++)
                    wmma::mma_sync(acc[i][j], af, bf[j], acc[i][j]);
            }
        }
        if (kt + 2 < KT) {
            int ns = stg + 2; if (ns >= NSTG) ns -= NSTG;
            load_tiles(A, B, Kdim, bm, bn, As, Bs, ns, (kt + 2) * BK, tid);
        } else {
            cp_commit();
        }
        if (++stg == NSTG) stg = 0;
    }
}

// ---------------- fused QKV projection (direct split-head fp16 epilogue) ----------------
// grid (8, 64, 3): x = 256-wide col tile (2 heads), y = row tile, z = projection
#define CSTR 264  // f32 stage stride: 256 + 8
__global__ __launch_bounds__(256, 1) void gemm_qkv_kernel(
    const __half* __restrict__ X,
    const __half* __restrict__ Wq, const __half* __restrict__ Wk, const __half* __restrict__ Wv,
    __half* __restrict__ Q, __half* __restrict__ K, __half* __restrict__ V) {
    extern __shared__ char smem[];
    __half* As = (__half*)smem;
    __half* Bs = As + NSTG * ABUF;

    const __half* Bw = (blockIdx.z == 0) ? Wq : (blockIdx.z == 1) ? Wk : Wv;
    __half* O = (blockIdx.z == 0) ? Q : (blockIdx.z == 1) ? K : V;

    const int tid = threadIdx.x, warp = tid >> 5;
    const int wr = warp >> 2, wc = warp & 3;
    const int bm = blockIdx.y * 128, bn = blockIdx.x * 256;

    wmma::fragment<wmma::accumulator, 16, 16, 16, float> acc[4][4];
#pragma unroll
    for (int i = 0; i < 4; i++)
#pragma unroll
        for (int j = 0; j < 4; j++) wmma::fill_fragment(acc[i][j], 0.0f);

    gemm_mainloop(X, Bw, DMv, bm, bn, As, Bs, acc, tid, wr, wc);

    // epilogue: stage f32 in smem, convert to fp16 split-head layout
    float* Cs = (float*)smem;  // 128 x CSTR
    __syncthreads();
#pragma unroll
    for (int i = 0; i < 4; i++)
#pragma unroll
        for (int j = 0; j < 4; j++)
            wmma::store_matrix_sync(&Cs[(wr * 64 + i * 16) * CSTR + wc * 64 + j * 16],
                                    acc[i][j], CSTR, wmma::mem_row_major);
    __syncthreads();

    const int b = bm >> 11, s0 = bm & (Sv - 1);
    // 128 rows x 32 chunks of 8 cols = 4096 chunks, 16 per thread
    for (int i = tid; i < 128 * 32; i += 256) {
        int r = i >> 5, ch = i & 31;
        int d = ch * 8;                      // 0..248
        int gcol = bn + d;
        int h = gcol >> 7, dk = gcol & 127;
        const float* cp = &Cs[r * CSTR + d];
        __half2 p0 = __floats2half2_rn(cp[0], cp[1]);
        __half2 p1 = __floats2half2_rn(cp[2], cp[3]);
        __half2 p2 = __floats2half2_rn(cp[4], cp[5]);
        __half2 p3 = __floats2half2_rn(cp[6], cp[7]);
        uint4 o;
        o.x = *(unsigned int*)&p0; o.y = *(unsigned int*)&p1;
        o.z = *(unsigned int*)&p2; o.w = *(unsigned int*)&p3;
        *(uint4*)&O[(((size_t)(b * Hv + h)) * Sv + s0 + r) * DKv + dk] = o;
    }
}

// ---------------- output projection GEMM (f32 out) ----------------
__global__ __launch_bounds__(256, 1) void gemm_out_kernel(
    const __half* __restrict__ A, const __half* __restrict__ Bw, float* __restrict__ C) {
    extern __shared__ char smem[];
    __half* As = (__half*)smem;
    __half* Bs = As + NSTG * ABUF;

    const int tid = threadIdx.x, warp = tid >> 5;
    const int wr = warp >> 2, wc = warp & 3;
    const int bm = blockIdx.y * 128, bn = blockIdx.x * 256;

    wmma::fragment<wmma::accumulator, 16, 16, 16, float> acc[4][4];
#pragma unroll
    for (int i = 0; i < 4; i++)
#pragma unroll
        for (int j = 0; j < 4; j++) wmma::fill_fragment(acc[i][j], 0.0f);

    gemm_mainloop(A, Bw, DMv, bm, bn, As, Bs, acc, tid, wr, wc);

#pragma unroll
    for (int i = 0; i < 4; i++)
#pragma unroll
        for (int j = 0; j < 4; j++) {
            float* cptr = &C[(size_t)(bm + wr * 64 + i * 16) * DMv + bn + wc * 64 + j * 16];
            wmma::store_matrix_sync(cptr, acc[i][j], DMv, wmma::mem_row_major);
        }
}

// ---------------- flash attention v2: warp-private softmax, O in registers ----------------
#define QSTR 136
#define SSTR 68
#define PSTR 72
#define OSTR 132

#define FLASH_SMEM (3 * 64 * QSTR * 2 /*Q,K,V*/ + 64 * SSTR * 4 /*Sc*/ + \
                    64 * PSTR * 2 /*P*/ + 64 * OSTR * 4 /*Ts*/)

__global__ __launch_bounds__(128, 2) void flash_kernel(
    const __half* __restrict__ Q, const __half* __restrict__ K,
    const __half* __restrict__ V, __half* __restrict__ Ch,
    const int* __restrict__ um_ptr) {
    extern __shared__ char smem[];
    __half* Qs = (__half*)smem;            // 64 x QSTR
    __half* Ks = Qs + 64 * QSTR;
    __half* Vs = Ks + 64 * QSTR;
    float*  Sc = (float*)(Vs + 64 * QSTR);
    __half* Ps = (__half*)(Sc + 64 * SSTR);
    float*  Ts = (float*)(Ps + 64 * PSTR);

    const int tid  = threadIdx.x;
    const int warp = tid >> 5;
    const int lane = tid & 31;
    const int qb = blockIdx.x;
    const int bh = blockIdx.y;
    const int um = *um_ptr;

    const int riw = lane >> 1;
    const int hf  = lane & 1;
    const int my_row = warp * 16 + riw;
    const int qg = qb * 64 + my_row;

    const __half* Qbase = Q + ((size_t)bh * Sv + qb * 64) * DKv;
#pragma unroll
    for (int t = 0; t < 8; t++) {
        int v = tid + t * 128;
        int r = v >> 4, c = (v & 15) * 8;
        *(uint4*)&Qs[r * QSTR + c] = *(const uint4*)&Qbase[r * DKv + c];
    }

    float O[64];
#pragma unroll
    for (int j = 0; j < 64; j++) O[j] = 0.0f;
    float m_r = -1e30f, l_r = 0.0f;

    const int kb_end = um ? qb : (Sv / 64 - 1);
    const float scale = 0.08838834764831845f;

    for (int kb = 0; kb <= kb_end; ++kb) {
        const __half* Kbase = K + ((size_t)bh * Sv + kb * 64) * DKv;
        const __half* Vbase = V + ((size_t)bh * Sv + kb * 64) * DKv;
#pragma unroll
        for (int t = 0; t < 8; t++) {
            int v = tid + t * 128;
            int r = v >> 4, c = (v & 15) * 8;
            *(uint4*)&Ks[r * QSTR + c] = *(const uint4*)&Kbase[r * DKv + c];
            *(uint4*)&Vs[r * QSTR + c] = *(const uint4*)&Vbase[r * DKv + c];
        }
        __syncthreads();

        // S = Q * K^T
        {
            wmma::fragment<wmma::accumulator, 16, 16, 16, float> sacc[4];
#pragma unroll
            for (int j = 0; j < 4; j++) wmma::fill_fragment(sacc[j], 0.0f);
#pragma unroll
            for (int kk = 0; kk < DKv; kk += 16) {
                wmma::fragment<wmma::matrix_a, 16, 16, 16, __half, wmma::row_major> qa;
                wmma::load_matrix_sync(qa, &Qs[(warp * 16) * QSTR + kk], QSTR);
#pragma unroll
                for (int j = 0; j < 4; j++) {
                    wmma::fragment<wmma::matrix_b, 16, 16, 16, __half, wmma::col_major> kf;
                    wmma::load_matrix_sync(kf, &Ks[(j * 16) * QSTR + kk], QSTR);
                    wmma::mma_sync(sacc[j], qa, kf, sacc[j]);
                }
            }
#pragma unroll
            for (int j = 0; j < 4; j++)
                wmma::store_matrix_sync(&Sc[(warp * 16) * SSTR + j * 16], sacc[j], SSTR,
                                        wmma::mem_row_major);
        }
        __syncwarp();

        // softmax (lane owns row riw, cols [hf*32, hf*32+32))
        float alpha;
        {
            float vals[32];
            float lmax = -1e30f;
#pragma unroll
            for (int c = 0; c < 32; c++) {
                int kc = hf * 32 + c;
                float v = Sc[(warp * 16 + riw) * SSTR + kc] * scale;
                if (um && (kb * 64 + kc) > qg) v = -1e30f;
                vals[c] = v;
                lmax = fmaxf(lmax, v);
            }
            lmax = fmaxf(lmax, __shfl_xor_sync(0xffffffffu, lmax, 1));
            float mn = fmaxf(m_r, lmax);
            alpha = __expf(m_r - mn);
            float lsum = 0.0f;
#pragma unroll
            for (int c = 0; c < 32; c++) {
                float p = __expf(vals[c] - mn);
                lsum += p;
                Ps[(warp * 16 + riw) * PSTR + hf * 32 + c] = __float2half(p);
            }
            lsum += __shfl_xor_sync(0xffffffffu, lsum, 1);
            l_r = l_r * alpha + lsum;
            m_r = mn;
        }
        __syncwarp();

        // T = P * V
        {
            wmma::fragment<wmma::accumulator, 16, 16, 16, float> oacc[8];
#pragma unroll
            for (int j = 0; j < 8; j++) wmma::fill_fragment(oacc[j], 0.0f);
#pragma unroll
            for (int kk = 0; kk < 64; kk += 16) {
                wmma::fragment<wmma::matrix_a, 16, 16, 16, __half, wmma::row_major> pa;
                wmma::load_matrix_sync(pa, &Ps[(warp * 16) * PSTR + kk], PSTR);
#pragma unroll
                for (int j = 0; j < 8; j++) {
                    wmma::fragment<wmma::matrix_b, 16, 16, 16, __half, wmma::row_major> vb;
                    wmma::load_matrix_sync(vb, &Vs[kk * QSTR + j * 16], QSTR);
                    wmma::mma_sync(oacc[j], pa, vb, oacc[j]);
                }
            }
#pragma unroll
            for (int j = 0; j < 8; j++)
                wmma::store_matrix_sync(&Ts[(warp * 16) * OSTR + j * 16], oacc[j], OSTR,
                                        wmma::mem_row_major);
        }
        __syncwarp();

        {
            const float* tr = &Ts[(warp * 16 + riw) * OSTR + hf * 64];
#pragma unroll
            for (int j = 0; j < 64; j++) O[j] = O[j] * alpha + tr[j];
        }
        __syncthreads();
    }

    // epilogue
    const int b = bh / Hv, h = bh % Hv;
    const float inv = 1.0f / l_r;
    __half* obase = Ch + (size_t)(b * Sv + qb * 64 + my_row) * DMv + h * DKv + hf * 64;
#pragma unroll
    for (int j0 = 0; j0 < 64; j0 += 8) {
        __half2 p0 = __floats2half2_rn(O[j0 + 0] * inv, O[j0 + 1] * inv);
        __half2 p1 = __floats2half2_rn(O[j0 + 2] * inv, O[j0 + 3] * inv);
        __half2 p2 = __floats2half2_rn(O[j0 + 4] * inv, O[j0 + 5] * inv);
        __half2 p3 = __floats2half2_rn(O[j0 + 6] * inv, O[j0 + 7] * inv);
        uint4 o;
        o.x = *(unsigned int*)&p0; o.y = *(unsigned int*)&p1;
        o.z = *(unsigned int*)&p2; o.w = *(unsigned int*)&p3;
        *(uint4*)&obase[j0] = o;
    }
}

// ---------------- launch ----------------
extern "C" void kernel_launch(void* const* d_in, const int* in_sizes, int n_in,
                              void* d_out, int out_size) {
    const float* x  = (const float*)d_in[0];
    const float* Wq = (const float*)d_in[1];
    const float* Wk = (const float*)d_in[2];
    const float* Wv = (const float*)d_in[3];
    const float* Wo = (const float*)d_in[4];
    const int*   um = (const int*)d_in[5];
    float* out = (float*)d_out;

    __half *Xh, *Wqh, *Wkh, *Wvh, *Woh, *Q, *K, *V, *Ch;
    cudaGetSymbolAddress((void**)&Xh,  g_Xh);
    cudaGetSymbolAddress((void**)&Wqh, g_Wqh);
    cudaGetSymbolAddress((void**)&Wkh, g_Wkh);
    cudaGetSymbolAddress((void**)&Wvh, g_Wvh);
    cudaGetSymbolAddress((void**)&Woh, g_Woh);
    cudaGetSymbolAddress((void**)&Q,   g_Q);
    cudaGetSymbolAddress((void**)&K,   g_K);
    cudaGetSymbolAddress((void**)&V,   g_V);
    cudaGetSymbolAddress((void**)&Ch,  g_Ch);

    f2h_kernel<<<2048, 256>>>((const float4*)x,  (uint4*)Xh,  Mv * DMv / 8);
    f2h_kernel<<<1024, 256>>>((const float4*)Wq, (uint4*)Wqh, DMv * DMv / 8);
    f2h_kernel<<<1024, 256>>>((const float4*)Wk, (uint4*)Wkh, DMv * DMv / 8);
    f2h_kernel<<<1024, 256>>>((const float4*)Wv, (uint4*)Wvh, DMv * DMv / 8);
    f2h_kernel<<<1024, 256>>>((const float4*)Wo, (uint4*)Woh, DMv * DMv / 8);

    cudaFuncSetAttribute(gemm_qkv_kernel, cudaFuncAttributeMaxDynamicSharedMemorySize, GEMM_SMEM);
    cudaFuncSetAttribute(gemm_out_kernel, cudaFuncAttributeMaxDynamicSharedMemorySize, GEMM_SMEM);
    cudaFuncSetAttribute(flash_kernel, cudaFuncAttributeMaxDynamicSharedMemorySize, FLASH_SMEM);

    gemm_qkv_kernel<<<dim3(8, 64, 3), 256, GEMM_SMEM>>>(Xh, Wqh, Wkh, Wvh, Q, K, V);

    flash_kernel<<<dim3(Sv / 64, Bv * Hv), 128, FLASH_SMEM>>>(Q, K, V, Ch, um);

    gemm_out_kernel<<<dim3(8, 64), 256, GEMM_SMEM>>>(Ch, Woh, out);
}

// round 11
// speedup vs baseline: 1.0878x; 1.0878x over previous
#include <cuda_runtime.h>
#include <cuda_fp16.h>
#include <mma.h>
#include <cstdint>

using namespace nvcuda;

// Problem constants
#define Bv 4
#define Sv 2048
#define Hv 16
#define DKv 128
#define DMv 2048
#define Mv (Bv * Sv)  // 8192

// ---------------- device scratch (static, allocation-free) ----------------
__device__ __half g_Xh [Mv * DMv];
__device__ __half g_Wqh[DMv * DMv];
__device__ __half g_Wkh[DMv * DMv];
__device__ __half g_Wvh[DMv * DMv];
__device__ __half g_Woh[DMv * DMv];
__device__ __half g_Q  [Mv * DMv];
__device__ __half g_K  [Mv * DMv];
__device__ __half g_V  [Mv * DMv];
__device__ __half g_Ch [Mv * DMv];

// ---------------- cp.async helpers ----------------
__device__ __forceinline__ void cp16(void* s, const void* g) {
    unsigned int sa = (unsigned int)__cvta_generic_to_shared(s);
    asm volatile("cp.async.cg.shared.global [%0], [%1], 16;\n" :: "r"(sa), "l"(g));
}
__device__ __forceinline__ void cp_commit() { asm volatile("cp.async.commit_group;\n"); }
template <int N>
__device__ __forceinline__ void cp_wait() { asm volatile("cp.async.wait_group %0;\n" :: "n"(N)); }

// ---------------- fp32 -> fp16 convert (vector 8) ----------------
__global__ void f2h_kernel(const float4* __restrict__ in, uint4* __restrict__ out, int n8) {
    int i = blockIdx.x * blockDim.x + threadIdx.x;
    int stride = gridDim.x * blockDim.x;
    for (; i < n8; i += stride) {
        float4 a = in[i * 2], b = in[i * 2 + 1];
        __half2 h0 = __floats2half2_rn(a.x, a.y);
        __half2 h1 = __floats2half2_rn(a.z, a.w);
        __half2 h2 = __floats2half2_rn(b.x, b.y);
        __half2 h3 = __floats2half2_rn(b.z, b.w);
        uint4 o;
        o.x = *(unsigned int*)&h0; o.y = *(unsigned int*)&h1;
        o.z = *(unsigned int*)&h2; o.w = *(unsigned int*)&h3;
        out[i] = o;
    }
}

// ---------------- GEMM: block 128x128, 4 warps (2x2), warp tile 64x64, BK=64, 3-stage ----------------
// 128 threads. wr = warp>>1 (0..1) -> 64 rows, wc = warp&1 (0..1) -> 64 cols.
// C[M,N] = A[M,K] * B[N,K]^T
#define BK 64
#define KSTR 72                     // halves: 64 + 8 pad
#define BUFH (128 * KSTR)           // halves per tile buffer
#define NSTG 3
#define GEMM_SMEM (NSTG * 2 * BUFH * 2)  // 110592 bytes -> 2 CTAs/SM

__device__ __forceinline__ void load_tiles(
    const __half* __restrict__ A, const __half* __restrict__ B, int Kdim,
    int bm, int bn, __half* As, __half* Bs, int stg, int k0, int tid) {
    // A and B: each 128 rows x 64 halves = 1024 uint4; 128 threads -> 8 iters each
#pragma unroll
    for (int t = 0; t < 8; t++) {
        int v = tid + t * 128;
        int r = v >> 3;
        int c = (v & 7) * 8;
        cp16(&As[stg * BUFH + r * KSTR + c], &A[(size_t)(bm + r) * Kdim + k0 + c]);
    }
#pragma unroll
    for (int t = 0; t < 8; t++) {
        int v = tid + t * 128;
        int r = v >> 3;
        int c = (v & 7) * 8;
        cp16(&Bs[stg * BUFH + r * KSTR + c], &B[(size_t)(bn + r) * Kdim + k0 + c]);
    }
    cp_commit();
}

__device__ __forceinline__ void gemm_mainloop(
    const __half* __restrict__ A, const __half* __restrict__ B, int Kdim,
    int bm, int bn, __half* As, __half* Bs,
    wmma::fragment<wmma::accumulator, 16, 16, 16, float> acc[4][4],
    int tid, int wr, int wc) {
    const int KT = Kdim / BK;
    load_tiles(A, B, Kdim, bm, bn, As, Bs, 0, 0, tid);
    load_tiles(A, B, Kdim, bm, bn, As, Bs, 1, BK, tid);
    int stg = 0;
    for (int kt = 0; kt < KT; ++kt) {
        cp_wait<1>();
        __syncthreads();
        const __half* Ab = &As[stg * BUFH];
        const __half* Bb = &Bs[stg * BUFH];
#pragma unroll
        for (int kk = 0; kk < BK; kk += 16) {
            wmma::fragment<wmma::matrix_b, 16, 16, 16, __half, wmma::col_major> bf[4];
#pragma unroll
            for (int j = 0; j < 4; j++)
                wmma::load_matrix_sync(bf[j], &Bb[(wc * 64 + j * 16) * KSTR + kk], KSTR);
#pragma unroll
            for (int i = 0; i < 4; i++) {
                wmma::fragment<wmma::matrix_a, 16, 16, 16, __half, wmma::row_major> af;
                wmma::load_matrix_sync(af, &Ab[(wr * 64 + i * 16) * KSTR + kk], KSTR);
#pragma unroll
                for (int j = 0; j < 4; j++)
                    wmma::mma_sync(acc[i][j], af, bf[j], acc[i][j]);
            }
        }
        if (kt + 2 < KT) {
            int ns = stg + 2; if (ns >= NSTG) ns -= NSTG;
            load_tiles(A, B, Kdim, bm, bn, As, Bs, ns, (kt + 2) * BK, tid);
        } else {
            cp_commit();
        }
        if (++stg == NSTG) stg = 0;
    }
}

// ---------------- fused QKV projection (direct split-head fp16 epilogue) ----------------
// grid (16, 64, 3): x = head (BN==DKv==128), y = row tile, z = which projection
__global__ __launch_bounds__(128, 2) void gemm_qkv_kernel(
    const __half* __restrict__ X,
    const __half* __restrict__ Wq, const __half* __restrict__ Wk, const __half* __restrict__ Wv,
    __half* __restrict__ Q, __half* __restrict__ K, __half* __restrict__ V) {
    extern __shared__ char smem[];
    __half* As = (__half*)smem;
    __half* Bs = As + NSTG * BUFH;

    const __half* Bw = (blockIdx.z == 0) ? Wq : (blockIdx.z == 1) ? Wk : Wv;
    __half* O = (blockIdx.z == 0) ? Q : (blockIdx.z == 1) ? K : V;

    const int tid = threadIdx.x, warp = tid >> 5;
    const int wr = warp >> 1, wc = warp & 1;
    const int bm = blockIdx.y * 128, bn = blockIdx.x * 128;

    wmma::fragment<wmma::accumulator, 16, 16, 16, float> acc[4][4];
#pragma unroll
    for (int i = 0; i < 4; i++)
#pragma unroll
        for (int j = 0; j < 4; j++) wmma::fill_fragment(acc[i][j], 0.0f);

    gemm_mainloop(X, Bw, DMv, bm, bn, As, Bs, acc, tid, wr, wc);

    // epilogue: stage f32 in smem, convert to fp16 split-head layout
    float* Cs = (float*)smem;  // 128 x 132
    __syncthreads();
#pragma unroll
    for (int i = 0; i < 4; i++)
#pragma unroll
        for (int j = 0; j < 4; j++)
            wmma::store_matrix_sync(&Cs[(wr * 64 + i * 16) * 132 + wc * 64 + j * 16],
                                    acc[i][j], 132, wmma::mem_row_major);
    __syncthreads();

    const int b = bm >> 11, s0 = bm & (Sv - 1), h = blockIdx.x;
    __half* Ob = O + (((size_t)(b * Hv + h)) * Sv + s0) * DKv;
    // 128 rows x 16 chunks of 8 = 2048 chunks, 16 per thread
    for (int i = tid; i < 128 * 16; i += 128) {
        int r = i >> 4, d = (i & 15) * 8;
        const float* cp = &Cs[r * 132 + d];
        __half2 p0 = __floats2half2_rn(cp[0], cp[1]);
        __half2 p1 = __floats2half2_rn(cp[2], cp[3]);
        __half2 p2 = __floats2half2_rn(cp[4], cp[5]);
        __half2 p3 = __floats2half2_rn(cp[6], cp[7]);
        uint4 o;
        o.x = *(unsigned int*)&p0; o.y = *(unsigned int*)&p1;
        o.z = *(unsigned int*)&p2; o.w = *(unsigned int*)&p3;
        *(uint4*)&Ob[r * DKv + d] = o;
    }
}

// ---------------- output projection GEMM (f32 out) ----------------
__global__ __launch_bounds__(128, 2) void gemm_out_kernel(
    const __half* __restrict__ A, const __half* __restrict__ Bw, float* __restrict__ C) {
    extern __shared__ char smem[];
    __half* As = (__half*)smem;
    __half* Bs = As + NSTG * BUFH;

    const int tid = threadIdx.x, warp = tid >> 5;
    const int wr = warp >> 1, wc = warp & 1;
    const int bm = blockIdx.y * 128, bn = blockIdx.x * 128;

    wmma::fragment<wmma::accumulator, 16, 16, 16, float> acc[4][4];
#pragma unroll
    for (int i = 0; i < 4; i++)
#pragma unroll
        for (int j = 0; j < 4; j++) wmma::fill_fragment(acc[i][j], 0.0f);

    gemm_mainloop(A, Bw, DMv, bm, bn, As, Bs, acc, tid, wr, wc);

#pragma unroll
    for (int i = 0; i < 4; i++)
#pragma unroll
        for (int j = 0; j < 4; j++) {
            float* cptr = &C[(size_t)(bm + wr * 64 + i * 16) * DMv + bn + wc * 64 + j * 16];
            wmma::store_matrix_sync(cptr, acc[i][j], DMv, wmma::mem_row_major);
        }
}

// ---------------- flash attention v2: warp-private softmax, O in registers ----------------
#define QSTR 136
#define SSTR 68
#define PSTR 72
#define OSTR 132

#define FLASH_SMEM (3 * 64 * QSTR * 2 /*Q,K,V*/ + 64 * SSTR * 4 /*Sc*/ + \
                    64 * PSTR * 2 /*P*/ + 64 * OSTR * 4 /*Ts*/)

__global__ __launch_bounds__(128, 2) void flash_kernel(
    const __half* __restrict__ Q, const __half* __restrict__ K,
    const __half* __restrict__ V, __half* __restrict__ Ch,
    const int* __restrict__ um_ptr) {
    extern __shared__ char smem[];
    __half* Qs = (__half*)smem;            // 64 x QSTR
    __half* Ks = Qs + 64 * QSTR;
    __half* Vs = Ks + 64 * QSTR;
    float*  Sc = (float*)(Vs + 64 * QSTR);
    __half* Ps = (__half*)(Sc + 64 * SSTR);
    float*  Ts = (float*)(Ps + 64 * PSTR);

    const int tid  = threadIdx.x;
    const int warp = tid >> 5;
    const int lane = tid & 31;
    const int qb = blockIdx.x;
    const int bh = blockIdx.y;
    const int um = *um_ptr;

    const int riw = lane >> 1;
    const int hf  = lane & 1;
    const int my_row = warp * 16 + riw;
    const int qg = qb * 64 + my_row;

    const __half* Qbase = Q + ((size_t)bh * Sv + qb * 64) * DKv;
#pragma unroll
    for (int t = 0; t < 8; t++) {
        int v = tid + t * 128;
        int r = v >> 4, c = (v & 15) * 8;
        *(uint4*)&Qs[r * QSTR + c] = *(const uint4*)&Qbase[r * DKv + c];
    }

    float O[64];
#pragma unroll
    for (int j = 0; j < 64; j++) O[j] = 0.0f;
    float m_r = -1e30f, l_r = 0.0f;

    const int kb_end = um ? qb : (Sv / 64 - 1);
    const float scale = 0.08838834764831845f;

    for (int kb = 0; kb <= kb_end; ++kb) {
        const __half* Kbase = K + ((size_t)bh * Sv + kb * 64) * DKv;
        const __half* Vbase = V + ((size_t)bh * Sv + kb * 64) * DKv;
#pragma unroll
        for (int t = 0; t < 8; t++) {
            int v = tid + t * 128;
            int r = v >> 4, c = (v & 15) * 8;
            *(uint4*)&Ks[r * QSTR + c] = *(const uint4*)&Kbase[r * DKv + c];
            *(uint4*)&Vs[r * QSTR + c] = *(const uint4*)&Vbase[r * DKv + c];
        }
        __syncthreads();

        // S = Q * K^T
        {
            wmma::fragment<wmma::accumulator, 16, 16, 16, float> sacc[4];
#pragma unroll
            for (int j = 0; j < 4; j++) wmma::fill_fragment(sacc[j], 0.0f);
#pragma unroll
            for (int kk = 0; kk < DKv; kk += 16) {
                wmma::fragment<wmma::matrix_a, 16, 16, 16, __half, wmma::row_major> qa;
                wmma::load_matrix_sync(qa, &Qs[(warp * 16) * QSTR + kk], QSTR);
#pragma unroll
                for (int j = 0; j < 4; j++) {
                    wmma::fragment<wmma::matrix_b, 16, 16, 16, __half, wmma::col_major> kf;
                    wmma::load_matrix_sync(kf, &Ks[(j * 16) * QSTR + kk], QSTR);
                    wmma::mma_sync(sacc[j], qa, kf, sacc[j]);
                }
            }
#pragma unroll
            for (int j = 0; j < 4; j++)
                wmma::store_matrix_sync(&Sc[(warp * 16) * SSTR + j * 16], sacc[j], SSTR,
                                        wmma::mem_row_major);
        }
        __syncwarp();

        // softmax (lane owns row riw, cols [hf*32, hf*32+32))
        float alpha;
        {
            float vals[32];
            float lmax = -1e30f;
#pragma unroll
            for (int c = 0; c < 32; c++) {
                int kc = hf * 32 + c;
                float v = Sc[(warp * 16 + riw) * SSTR + kc] * scale;
                if (um && (kb * 64 + kc) > qg) v = -1e30f;
                vals[c] = v;
                lmax = fmaxf(lmax, v);
            }
            lmax = fmaxf(lmax, __shfl_xor_sync(0xffffffffu, lmax, 1));
            float mn = fmaxf(m_r, lmax);
            alpha = __expf(m_r - mn);
            float lsum = 0.0f;
#pragma unroll
            for (int c = 0; c < 32; c++) {
                float p = __expf(vals[c] - mn);
                lsum += p;
                Ps[(warp * 16 + riw) * PSTR + hf * 32 + c] = __float2half(p);
            }
            lsum += __shfl_xor_sync(0xffffffffu, lsum, 1);
            l_r = l_r * alpha + lsum;
            m_r = mn;
        }
        __syncwarp();

        // T = P * V
        {
            wmma::fragment<wmma::accumulator, 16, 16, 16, float> oacc[8];
#pragma unroll
            for (int j = 0; j < 8; j++) wmma::fill_fragment(oacc[j], 0.0f);
#pragma unroll
            for (int kk = 0; kk < 64; kk += 16) {
                wmma::fragment<wmma::matrix_a, 16, 16, 16, __half, wmma::row_major> pa;
                wmma::load_matrix_sync(pa, &Ps[(warp * 16) * PSTR + kk], PSTR);
#pragma unroll
                for (int j = 0; j < 8; j++) {
                    wmma::fragment<wmma::matrix_b, 16, 16, 16, __half, wmma::row_major> vb;
                    wmma::load_matrix_sync(vb, &Vs[kk * QSTR + j * 16], QSTR);
                    wmma::mma_sync(oacc[j], pa, vb, oacc[j]);
                }
            }
#pragma unroll
            for (int j = 0; j < 8; j++)
                wmma::store_matrix_sync(&Ts[(warp * 16) * OSTR + j * 16], oacc[j], OSTR,
                                        wmma::mem_row_major);
        }
        __syncwarp();

        {
            const float* tr = &Ts[(warp * 16 + riw) * OSTR + hf * 64];
#pragma unroll
            for (int j = 0; j < 64; j++) O[j] = O[j] * alpha + tr[j];
        }
        __syncthreads();
    }

    // epilogue
    const int b = bh / Hv, h = bh % Hv;
    const float inv = 1.0f / l_r;
    __half* obase = Ch + (size_t)(b * Sv + qb * 64 + my_row) * DMv + h * DKv + hf * 64;
#pragma unroll
    for (int j0 = 0; j0 < 64; j0 += 8) {
        __half2 p0 = __floats2half2_rn(O[j0 + 0] * inv, O[j0 + 1] * inv);
        __half2 p1 = __floats2half2_rn(O[j0 + 2] * inv, O[j0 + 3] * inv);
        __half2 p2 = __floats2half2_rn(O[j0 + 4] * inv, O[j0 + 5] * inv);
        __half2 p3 = __floats2half2_rn(O[j0 + 6] * inv, O[j0 + 7] * inv);
        uint4 o;
        o.x = *(unsigned int*)&p0; o.y = *(unsigned int*)&p1;
        o.z = *(unsigned int*)&p2; o.w = *(unsigned int*)&p3;
        *(uint4*)&obase[j0] = o;
    }
}

// ---------------- launch ----------------
extern "C" void kernel_launch(void* const* d_in, const int* in_sizes, int n_in,
                              void* d_out, int out_size) {
    const float* x  = (const float*)d_in[0];
    const float* Wq = (const float*)d_in[1];
    const float* Wk = (const float*)d_in[2];
    const float* Wv = (const float*)d_in[3];
    const float* Wo = (const float*)d_in[4];
    const int*   um = (const int*)d_in[5];
    float* out = (float*)d_out;

    __half *Xh, *Wqh, *Wkh, *Wvh, *Woh, *Q, *K, *V, *Ch;
    cudaGetSymbolAddress((void**)&Xh,  g_Xh);
    cudaGetSymbolAddress((void**)&Wqh, g_Wqh);
    cudaGetSymbolAddress((void**)&Wkh, g_Wkh);
    cudaGetSymbolAddress((void**)&Wvh, g_Wvh);
    cudaGetSymbolAddress((void**)&Woh, g_Woh);
    cudaGetSymbolAddress((void**)&Q,   g_Q);
    cudaGetSymbolAddress((void**)&K,   g_K);
    cudaGetSymbolAddress((void**)&V,   g_V);
    cudaGetSymbolAddress((void**)&Ch,  g_Ch);

    f2h_kernel<<<2048, 256>>>((const float4*)x,  (uint4*)Xh,  Mv * DMv / 8);
    f2h_kernel<<<1024, 256>>>((const float4*)Wq, (uint4*)Wqh, DMv * DMv / 8);
    f2h_kernel<<<1024, 256>>>((const float4*)Wk, (uint4*)Wkh, DMv * DMv / 8);
    f2h_kernel<<<1024, 256>>>((const float4*)Wv, (uint4*)Wvh, DMv * DMv / 8);
    f2h_kernel<<<1024, 256>>>((const float4*)Wo, (uint4*)Woh, DMv * DMv / 8);

    cudaFuncSetAttribute(gemm_qkv_kernel, cudaFuncAttributeMaxDynamicSharedMemorySize, GEMM_SMEM);
    cudaFuncSetAttribute(gemm_out_kernel, cudaFuncAttributeMaxDynamicSharedMemorySize, GEMM_SMEM);
    cudaFuncSetAttribute(flash_kernel, cudaFuncAttributeMaxDynamicSharedMemorySize, FLASH_SMEM);

    gemm_qkv_kernel<<<dim3(16, 64, 3), 128, GEMM_SMEM>>>(Xh, Wqh, Wkh, Wvh, Q, K, V);

    flash_kernel<<<dim3(Sv / 64, Bv * Hv), 128, FLASH_SMEM>>>(Q, K, V, Ch, um);

    gemm_out_kernel<<<dim3(16, 64), 128, GEMM_SMEM>>>(Ch, Woh, out);
}

// round 13
// speedup vs baseline: 1.3428x; 1.2344x over previous
#include <cuda_runtime.h>
#include <cuda_fp16.h>
#include <mma.h>
#include <cstdint>

using namespace nvcuda;

// Problem constants
#define Bv 4
#define Sv 2048
#define Hv 16
#define DKv 128
#define DMv 2048
#define Mv (Bv * Sv)  // 8192

// ---------------- device scratch (static, allocation-free) ----------------
__device__ __half g_Xh [Mv * DMv];
__device__ __half g_Wqh[DMv * DMv];
__device__ __half g_Wkh[DMv * DMv];
__device__ __half g_Wvh[DMv * DMv];
__device__ __half g_Woh[DMv * DMv];
__device__ __half g_Q  [Mv * DMv];
__device__ __half g_K  [Mv * DMv];
__device__ __half g_V  [Mv * DMv];
__device__ __half g_Ch [Mv * DMv];

// ---------------- cp.async helpers ----------------
__device__ __forceinline__ void cp16(void* s, const void* g) {
    unsigned int sa = (unsigned int)__cvta_generic_to_shared(s);
    asm volatile("cp.async.cg.shared.global [%0], [%1], 16;\n" :: "r"(sa), "l"(g));
}
__device__ __forceinline__ void cp_commit() { asm volatile("cp.async.commit_group;\n"); }
template <int N>
__device__ __forceinline__ void cp_wait() { asm volatile("cp.async.wait_group %0;\n" :: "n"(N)); }

__device__ __forceinline__ uint32_t smem_to_u32(const void* smem_ptr) {
    uint32_t addr;
    asm("{ .reg .u64 tmp; cvta.to.shared.u64 tmp, %1; cvt.u32.u64 %0, tmp; }"
        : "=r"(addr) : "l"(smem_ptr));
    return addr;
}

// ---------------- mma.sync / ldmatrix helpers ----------------
__device__ __forceinline__ void ldsm4(uint32_t* r, uint32_t a) {
    asm volatile("ldmatrix.sync.aligned.m8n8.x4.shared.b16 {%0,%1,%2,%3}, [%4];"
        : "=r"(r[0]), "=r"(r[1]), "=r"(r[2]), "=r"(r[3]) : "r"(a));
}
__device__ __forceinline__ void ldsm4t(uint32_t* r, uint32_t a) {
    asm volatile("ldmatrix.sync.aligned.m8n8.x4.trans.shared.b16 {%0,%1,%2,%3}, [%4];"
        : "=r"(r[0]), "=r"(r[1]), "=r"(r[2]), "=r"(r[3]) : "r"(a));
}
__device__ __forceinline__ void mma_16816(float* c, uint32_t a0, uint32_t a1, uint32_t a2,
                                          uint32_t a3, uint32_t b0, uint32_t b1) {
    asm volatile(
        "mma.sync.aligned.m16n8k16.row.col.f32.f16.f16.f32 "
        "{%0,%1,%2,%3}, {%4,%5,%6,%7}, {%8,%9}, {%0,%1,%2,%3};"
        : "+f"(c[0]), "+f"(c[1]), "+f"(c[2]), "+f"(c[3])
        : "r"(a0), "r"(a1), "r"(a2), "r"(a3), "r"(b0), "r"(b1));
}

// ---------------- fp32 -> fp16 convert (vector 8) ----------------
__global__ void f2h_kernel(const float4* __restrict__ in, uint4* __restrict__ out, int n8) {
    int i = blockIdx.x * blockDim.x + threadIdx.x;
    int stride = gridDim.x * blockDim.x;
    for (; i < n8; i += stride) {
        float4 a = in[i * 2], b = in[i * 2 + 1];
        __half2 h0 = __floats2half2_rn(a.x, a.y);
        __half2 h1 = __floats2half2_rn(a.z, a.w);
        __half2 h2 = __floats2half2_rn(b.x, b.y);
        __half2 h3 = __floats2half2_rn(b.z, b.w);
        uint4 o;
        o.x = *(unsigned int*)&h0; o.y = *(unsigned int*)&h1;
        o.z = *(unsigned int*)&h2; o.w = *(unsigned int*)&h3;
        out[i] = o;
    }
}

// ---------------- GEMM: block 128x128, 4 warps (2x2), warp tile 64x64, BK=64, 3-stage ----------------
#define BK 64
#define KSTR 72
#define BUFH (128 * KSTR)
#define NSTG 3
#define GEMM_SMEM (NSTG * 2 * BUFH * 2)  // 110592 bytes -> 2 CTAs/SM

__device__ __forceinline__ void load_tiles(
    const __half* __restrict__ A, const __half* __restrict__ B, int Kdim,
    int bm, int bn, __half* As, __half* Bs, int stg, int k0, int tid) {
#pragma unroll
    for (int t = 0; t < 8; t++) {
        int v = tid + t * 128;
        int r = v >> 3;
        int c = (v & 7) * 8;
        cp16(&As[stg * BUFH + r * KSTR + c], &A[(size_t)(bm + r) * Kdim + k0 + c]);
    }
#pragma unroll
    for (int t = 0; t < 8; t++) {
        int v = tid + t * 128;
        int r = v >> 3;
        int c = (v & 7) * 8;
        cp16(&Bs[stg * BUFH + r * KSTR + c], &B[(size_t)(bn + r) * Kdim + k0 + c]);
    }
    cp_commit();
}

__device__ __forceinline__ void gemm_mainloop(
    const __half* __restrict__ A, const __half* __restrict__ B, int Kdim,
    int bm, int bn, __half* As, __half* Bs,
    wmma::fragment<wmma::accumulator, 16, 16, 16, float> acc[4][4],
    int tid, int wr, int wc) {
    const int KT = Kdim / BK;
    load_tiles(A, B, Kdim, bm, bn, As, Bs, 0, 0, tid);
    load_tiles(A, B, Kdim, bm, bn, As, Bs, 1, BK, tid);
    int stg = 0;
    for (int kt = 0; kt < KT; ++kt) {
        cp_wait<1>();
        __syncthreads();
        const __half* Ab = &As[stg * BUFH];
        const __half* Bb = &Bs[stg * BUFH];
#pragma unroll
        for (int kk = 0; kk < BK; kk += 16) {
            wmma::fragment<wmma::matrix_b, 16, 16, 16, __half, wmma::col_major> bf[4];
#pragma unroll
            for (int j = 0; j < 4; j++)
                wmma::load_matrix_sync(bf[j], &Bb[(wc * 64 + j * 16) * KSTR + kk], KSTR);
#pragma unroll
            for (int i = 0; i < 4; i++) {
                wmma::fragment<wmma::matrix_a, 16, 16, 16, __half, wmma::row_major> af;
                wmma::load_matrix_sync(af, &Ab[(wr * 64 + i * 16) * KSTR + kk], KSTR);
#pragma unroll
                for (int j = 0; j < 4; j++)
                    wmma::mma_sync(acc[i][j], af, bf[j], acc[i][j]);
            }
        }
        if (kt + 2 < KT) {
            int ns = stg + 2; if (ns >= NSTG) ns -= NSTG;
            load_tiles(A, B, Kdim, bm, bn, As, Bs, ns, (kt + 2) * BK, tid);
        } else {
            cp_commit();
        }
        if (++stg == NSTG) stg = 0;
    }
}

// ---------------- fused QKV projection (direct split-head fp16 epilogue) ----------------
__global__ __launch_bounds__(128, 2) void gemm_qkv_kernel(
    const __half* __restrict__ X,
    const __half* __restrict__ Wq, const __half* __restrict__ Wk, const __half* __restrict__ Wv,
    __half* __restrict__ Q, __half* __restrict__ K, __half* __restrict__ V) {
    extern __shared__ char smem[];
    __half* As = (__half*)smem;
    __half* Bs = As + NSTG * BUFH;

    const __half* Bw = (blockIdx.z == 0) ? Wq : (blockIdx.z == 1) ? Wk : Wv;
    __half* O = (blockIdx.z == 0) ? Q : (blockIdx.z == 1) ? K : V;

    const int tid = threadIdx.x, warp = tid >> 5;
    const int wr = warp >> 1, wc = warp & 1;
    const int bm = blockIdx.y * 128, bn = blockIdx.x * 128;

    wmma::fragment<wmma::accumulator, 16, 16, 16, float> acc[4][4];
#pragma unroll
    for (int i = 0; i < 4; i++)
#pragma unroll
        for (int j = 0; j < 4; j++) wmma::fill_fragment(acc[i][j], 0.0f);

    gemm_mainloop(X, Bw, DMv, bm, bn, As, Bs, acc, tid, wr, wc);

    float* Cs = (float*)smem;  // 128 x 132
    __syncthreads();
#pragma unroll
    for (int i = 0; i < 4; i++)
#pragma unroll
        for (int j = 0; j < 4; j++)
            wmma::store_matrix_sync(&Cs[(wr * 64 + i * 16) * 132 + wc * 64 + j * 16],
                                    acc[i][j], 132, wmma::mem_row_major);
    __syncthreads();

    const int b = bm >> 11, s0 = bm & (Sv - 1), h = blockIdx.x;
    __half* Ob = O + (((size_t)(b * Hv + h)) * Sv + s0) * DKv;
    for (int i = tid; i < 128 * 16; i += 128) {
        int r = i >> 4, d = (i & 15) * 8;
        const float* cp = &Cs[r * 132 + d];
        __half2 p0 = __floats2half2_rn(cp[0], cp[1]);
        __half2 p1 = __floats2half2_rn(cp[2], cp[3]);
        __half2 p2 = __floats2half2_rn(cp[4], cp[5]);
        __half2 p3 = __floats2half2_rn(cp[6], cp[7]);
        uint4 o;
        o.x = *(unsigned int*)&p0; o.y = *(unsigned int*)&p1;
        o.z = *(unsigned int*)&p2; o.w = *(unsigned int*)&p3;
        *(uint4*)&Ob[r * DKv + d] = o;
    }
}

// ---------------- output projection GEMM (f32 out) ----------------
__global__ __launch_bounds__(128, 2) void gemm_out_kernel(
    const __half* __restrict__ A, const __half* __restrict__ Bw, float* __restrict__ C) {
    extern __shared__ char smem[];
    __half* As = (__half*)smem;
    __half* Bs = As + NSTG * BUFH;

    const int tid = threadIdx.x, warp = tid >> 5;
    const int wr = warp >> 1, wc = warp & 1;
    const int bm = blockIdx.y * 128, bn = blockIdx.x * 128;

    wmma::fragment<wmma::accumulator, 16, 16, 16, float> acc[4][4];
#pragma unroll
    for (int i = 0; i < 4; i++)
#pragma unroll
        for (int j = 0; j < 4; j++) wmma::fill_fragment(acc[i][j], 0.0f);

    gemm_mainloop(A, Bw, DMv, bm, bn, As, Bs, acc, tid, wr, wc);

#pragma unroll
    for (int i = 0; i < 4; i++)
#pragma unroll
        for (int j = 0; j < 4; j++) {
            float* cptr = &C[(size_t)(bm + wr * 64 + i * 16) * DMv + bn + wc * 64 + j * 16];
            wmma::store_matrix_sync(cptr, acc[i][j], DMv, wmma::mem_row_major);
        }
}

// ---------------- flash attention v3: FA2 register-resident (mma.sync + ldmatrix) ----------------
// Grid (S/64, B*H), 128 threads (4 warps). Each warp owns 16 query rows.
// S and O live in mma fragments; softmax fully in registers; smem = Q/K/V tiles only.
#define QSTR 136   // halves stride: 128 + 8 (272 B rows -> ldmatrix conflict-free)
#define FLASH_SMEM (3 * 64 * QSTR * 2)   // 52224 bytes

__global__ __launch_bounds__(128, 2) void flash_kernel(
    const __half* __restrict__ Q, const __half* __restrict__ K,
    const __half* __restrict__ V, __half* __restrict__ Ch,
    const int* __restrict__ um_ptr) {
    extern __shared__ char smem[];
    __half* Qs = (__half*)smem;            // 64 x QSTR
    __half* Ks = Qs + 64 * QSTR;
    __half* Vs = Ks + 64 * QSTR;
    const uint32_t Qs_u = smem_to_u32(Qs);
    const uint32_t Ks_u = Qs_u + 64 * QSTR * 2;
    const uint32_t Vs_u = Ks_u + 64 * QSTR * 2;

    const int tid  = threadIdx.x;
    const int warp = tid >> 5;
    const int lane = tid & 31;
    const int qb = blockIdx.x;
    const int bh = blockIdx.y;
    const int um = *um_ptr;

    // load Q tile + first K/V tiles
    const __half* Qb  = Q + ((size_t)bh * Sv + qb * 64) * DKv;
    const __half* Kb0 = K + ((size_t)bh * Sv) * DKv;
    const __half* Vb0 = V + ((size_t)bh * Sv) * DKv;
#pragma unroll
    for (int t = 0; t < 8; t++) {
        int v = tid + t * 128;
        int r = v >> 4, c = (v & 15) * 8;
        *(uint4*)&Qs[r * QSTR + c] = *(const uint4*)&Qb [r * DKv + c];
        *(uint4*)&Ks[r * QSTR + c] = *(const uint4*)&Kb0[r * DKv + c];
        *(uint4*)&Vs[r * QSTR + c] = *(const uint4*)&Vb0[r * DKv + c];
    }
    __syncthreads();

    // preload Q a-fragments (8 k-steps of 16): x4 = [rows0-7,k0-7][rows8-15,k0-7][rows0-7,k8-15][rows8-15,k8-15]
    uint32_t qa[8][4];
    {
        int sub = lane >> 3, i = lane & 7;
        int row = warp * 16 + i + (sub & 1) * 8;
        uint32_t base = Qs_u + (uint32_t)(row * QSTR + (sub >> 1) * 8) * 2;
#pragma unroll
        for (int t = 0; t < 8; t++) ldsm4(qa[t], base + t * 32);
    }

    float O[16][4];
#pragma unroll
    for (int j = 0; j < 16; j++) { O[j][0] = O[j][1] = O[j][2] = O[j][3] = 0.0f; }
    float m_lo = -1e30f, m_hi = -1e30f, l_lo = 0.0f, l_hi = 0.0f;

    const float scale = 0.08838834764831845f;  // 1/sqrt(128)
    const int kb_end = um ? qb : (Sv / 64 - 1);
    const int q_lo = qb * 64 + warp * 16 + (lane >> 2);  // sequence index of thread's low row

    for (int kb = 0; kb <= kb_end; ++kb) {
        if (kb > 0) {
            __syncthreads();   // prior iter's ldmatrix reads done
            const __half* Kb = K + ((size_t)bh * Sv + kb * 64) * DKv;
            const __half* Vb = V + ((size_t)bh * Sv + kb * 64) * DKv;
#pragma unroll
            for (int t = 0; t < 8; t++) {
                int v = tid + t * 128;
                int r = v >> 4, c = (v & 15) * 8;
                *(uint4*)&Ks[r * QSTR + c] = *(const uint4*)&Kb[r * DKv + c];
                *(uint4*)&Vs[r * QSTR + c] = *(const uint4*)&Vb[r * DKv + c];
            }
            __syncthreads();
        }

        // ---- S = Q K^T : 8 n-blocks (8 keys each) x c[4] ----
        float sc[8][4];
#pragma unroll
        for (int j = 0; j < 8; j++) { sc[j][0] = sc[j][1] = sc[j][2] = sc[j][3] = 0.0f; }
#pragma unroll
        for (int j = 0; j < 8; j++) {
            uint32_t ka = Ks_u + (uint32_t)((j * 8 + (lane & 7)) * QSTR + (lane >> 3) * 8) * 2;
#pragma unroll
            for (int t2 = 0; t2 < 8; t2 += 2) {
                uint32_t kf[4];
                ldsm4(kf, ka + t2 * 32);
                mma_16816(sc[j], qa[t2][0], qa[t2][1], qa[t2][2], qa[t2][3], kf[0], kf[1]);
                mma_16816(sc[j], qa[t2+1][0], qa[t2+1][1], qa[t2+1][2], qa[t2+1][3], kf[2], kf[3]);
            }
        }

        // ---- scale + causal mask + row max (rows: lo = lane>>2, hi = +8) ----
        float nm_lo = -1e30f, nm_hi = -1e30f;
        const bool diag = (um != 0) && (kb == qb);
#pragma unroll
        for (int j = 0; j < 8; j++) {
            sc[j][0] *= scale; sc[j][1] *= scale; sc[j][2] *= scale; sc[j][3] *= scale;
            if (diag) {
                int k0 = kb * 64 + 8 * j + 2 * (lane & 3);
                if (k0     > q_lo)     sc[j][0] = -1e30f;
                if (k0 + 1 > q_lo)     sc[j][1] = -1e30f;
                if (k0     > q_lo + 8) sc[j][2] = -1e30f;
                if (k0 + 1 > q_lo + 8) sc[j][3] = -1e30f;
            }
            nm_lo = fmaxf(nm_lo, fmaxf(sc[j][0], sc[j][1]));
            nm_hi = fmaxf(nm_hi, fmaxf(sc[j][2], sc[j][3]));
        }
        nm_lo = fmaxf(nm_lo, __shfl_xor_sync(0xffffffffu, nm_lo, 1));
        nm_lo = fmaxf(nm_lo, __shfl_xor_sync(0xffffffffu, nm_lo, 2));
        nm_hi = fmaxf(nm_hi, __shfl_xor_sync(0xffffffffu, nm_hi, 1));
        nm_hi = fmaxf(nm_hi, __shfl_xor_sync(0xffffffffu, nm_hi, 2));

        float mn_lo = fmaxf(m_lo, nm_lo), mn_hi = fmaxf(m_hi, nm_hi);
        float al = __expf(m_lo - mn_lo), ah = __expf(m_hi - mn_hi);
        m_lo = mn_lo; m_hi = mn_hi;

        // ---- P = exp(S - m): pack into PV a-fragments; row sums ----
        uint32_t pa[4][4];
        float rs_lo = 0.0f, rs_hi = 0.0f;
#pragma unroll
        for (int t = 0; t < 4; t++) {
            int j0 = 2 * t, j1 = 2 * t + 1;
            float e0 = __expf(sc[j0][0] - mn_lo), e1 = __expf(sc[j0][1] - mn_lo);
            float e2 = __expf(sc[j0][2] - mn_hi), e3 = __expf(sc[j0][3] - mn_hi);
            float f0 = __expf(sc[j1][0] - mn_lo), f1 = __expf(sc[j1][1] - mn_lo);
            float f2 = __expf(sc[j1][2] - mn_hi), f3 = __expf(sc[j1][3] - mn_hi);
            rs_lo += e0 + e1 + f0 + f1;
            rs_hi += e2 + e3 + f2 + f3;
            __half2 h;
            h = __floats2half2_rn(e0, e1); pa[t][0] = *(unsigned int*)&h;
            h = __floats2half2_rn(e2, e3); pa[t][1] = *(unsigned int*)&h;
            h = __floats2half2_rn(f0, f1); pa[t][2] = *(unsigned int*)&h;
            h = __floats2half2_rn(f2, f3); pa[t][3] = *(unsigned int*)&h;
        }
        rs_lo += __shfl_xor_sync(0xffffffffu, rs_lo, 1);
        rs_lo += __shfl_xor_sync(0xffffffffu, rs_lo, 2);
        rs_hi += __shfl_xor_sync(0xffffffffu, rs_hi, 1);
        rs_hi += __shfl_xor_sync(0xffffffffu, rs_hi, 2);
        l_lo = l_lo * al + rs_lo;
        l_hi = l_hi * ah + rs_hi;

        // ---- rescale O in registers ----
#pragma unroll
        for (int j = 0; j < 16; j++) {
            O[j][0] *= al; O[j][1] *= al; O[j][2] *= ah; O[j][3] *= ah;
        }

        // ---- O += P V : 4 k-steps x 16 d-blocks; V b-frags via ldmatrix.trans ----
#pragma unroll
        for (int t = 0; t < 4; t++) {
            uint32_t va = Vs_u +
                (uint32_t)((16 * t + (lane & 7) + ((lane >> 3) & 1) * 8) * QSTR +
                           (lane >> 4) * 8) * 2;
#pragma unroll
            for (int jp = 0; jp < 8; jp++) {
                uint32_t vf[4];
                ldsm4t(vf, va + jp * 32);
                mma_16816(O[2*jp],   pa[t][0], pa[t][1], pa[t][2], pa[t][3], vf[0], vf[1]);
                mma_16816(O[2*jp+1], pa[t][0], pa[t][1], pa[t][2], pa[t][3], vf[2], vf[3]);
            }
        }
    }

    // ---- epilogue: divide by l, write fp16 ctx merged as [B, S, H*DK] ----
    const float il = 1.0f / l_lo, ih = 1.0f / l_hi;
    const int b = bh / Hv, h = bh % Hv;
    __half* p_lo = Ch + (size_t)(b * Sv + q_lo) * DMv + h * DKv + 2 * (lane & 3);
    __half* p_hi = p_lo + 8 * (size_t)DMv;
#pragma unroll
    for (int j = 0; j < 16; j++) {
        __half2 lo = __floats2half2_rn(O[j][0] * il, O[j][1] * il);
        __half2 hi = __floats2half2_rn(O[j][2] * ih, O[j][3] * ih);
        *(__half2*)&p_lo[8 * j] = lo;
        *(__half2*)&p_hi[8 * j] = hi;
    }
}

// ---------------- launch ----------------
extern "C" void kernel_launch(void* const* d_in, const int* in_sizes, int n_in,
                              void* d_out, int out_size) {
    const float* x  = (const float*)d_in[0];
    const float* Wq = (const float*)d_in[1];
    const float* Wk = (const float*)d_in[2];
    const float* Wv = (const float*)d_in[3];
    const float* Wo = (const float*)d_in[4];
    const int*   um = (const int*)d_in[5];
    float* out = (float*)d_out;

    __half *Xh, *Wqh, *Wkh, *Wvh, *Woh, *Q, *K, *V, *Ch;
    cudaGetSymbolAddress((void**)&Xh,  g_Xh);
    cudaGetSymbolAddress((void**)&Wqh, g_Wqh);
    cudaGetSymbolAddress((void**)&Wkh, g_Wkh);
    cudaGetSymbolAddress((void**)&Wvh, g_Wvh);
    cudaGetSymbolAddress((void**)&Woh, g_Woh);
    cudaGetSymbolAddress((void**)&Q,   g_Q);
    cudaGetSymbolAddress((void**)&K,   g_K);
    cudaGetSymbolAddress((void**)&V,   g_V);
    cudaGetSymbolAddress((void**)&Ch,  g_Ch);

    f2h_kernel<<<2048, 256>>>((const float4*)x,  (uint4*)Xh,  Mv * DMv / 8);
    f2h_kernel<<<1024, 256>>>((const float4*)Wq, (uint4*)Wqh, DMv * DMv / 8);
    f2h_kernel<<<1024, 256>>>((const float4*)Wk, (uint4*)Wkh, DMv * DMv / 8);
    f2h_kernel<<<1024, 256>>>((const float4*)Wv, (uint4*)Wvh, DMv * DMv / 8);
    f2h_kernel<<<1024, 256>>>((const float4*)Wo, (uint4*)Woh, DMv * DMv / 8);

    cudaFuncSetAttribute(gemm_qkv_kernel, cudaFuncAttributeMaxDynamicSharedMemorySize, GEMM_SMEM);
    cudaFuncSetAttribute(gemm_out_kernel, cudaFuncAttributeMaxDynamicSharedMemorySize, GEMM_SMEM);
    cudaFuncSetAttribute(flash_kernel, cudaFuncAttributeMaxDynamicSharedMemorySize, FLASH_SMEM);

    gemm_qkv_kernel<<<dim3(16, 64, 3), 128, GEMM_SMEM>>>(Xh, Wqh, Wkh, Wvh, Q, K, V);

    flash_kernel<<<dim3(Sv / 64, Bv * Hv), 128, FLASH_SMEM>>>(Q, K, V, Ch, um);

    gemm_out_kernel<<<dim3(16, 64), 128, GEMM_SMEM>>>(Ch, Woh, out);
}